// round 10
// baseline (speedup 1.0000x reference)
#include <cuda_runtime.h>
#include <cuda_bf16.h>
#include <math.h>
#include <stdint.h>

// ---------------------------------------------------------------- constants
#define NN 8192
#define DD 256
#define KX 512
#define EE 262144
#define H4 64
#define BM 128           // CTA tile M
#define BN 256           // CTA tile N
#define BK 64            // K chunk (bf16)
#define NTHREADS 512     // 16 warps, warp tile 32x64
#define NSPLIT 8         // split-K for gemm2

// ---------------------------------------------------------------- scratch
__device__ float         g_scores[(size_t)NN * NN];
__device__ __nv_bfloat16 g_Xhi[(size_t)NN * KX];
__device__ __nv_bfloat16 g_Xlo[(size_t)NN * KX];
__device__ __nv_bfloat16 g_Wthi[(size_t)KX * NN];
__device__ __nv_bfloat16 g_Wtlo[(size_t)KX * NN];
__device__ __nv_bfloat16 g_Ahi[(size_t)NN * NN];
__device__ __nv_bfloat16 g_Alo[(size_t)NN * NN];
__device__ float         g_part[(size_t)NSPLIT * NN * KX];
__device__ float         g_probe[32];

// ---------------------------------------------------------------- PTX utils
__device__ __forceinline__ uint32_t smem_u32(const void* p) {
    uint32_t a;
    asm("{ .reg .u64 t; cvta.to.shared.u64 t, %1; cvt.u32.u64 %0, t; }"
        : "=r"(a) : "l"(p));
    return a;
}
__device__ __forceinline__ void cp16(uint32_t dst, const void* src) {
    asm volatile("cp.async.cg.shared.global [%0], [%1], 16;"
                 :: "r"(dst), "l"(src) : "memory");
}
#define CP_COMMIT() asm volatile("cp.async.commit_group;" ::: "memory")
#define CP_WAIT1()  asm volatile("cp.async.wait_group 1;" ::: "memory")
#define CP_WAIT0()  asm volatile("cp.async.wait_group 0;" ::: "memory")

__device__ __forceinline__ void ldmx4(uint32_t& r0, uint32_t& r1,
                                      uint32_t& r2, uint32_t& r3, uint32_t a) {
    asm volatile("ldmatrix.sync.aligned.m8n8.x4.shared.b16 {%0,%1,%2,%3}, [%4];"
                 : "=r"(r0), "=r"(r1), "=r"(r2), "=r"(r3) : "r"(a));
}
__device__ __forceinline__ void mma16816(float* c, const uint32_t* a,
                                         uint32_t b0, uint32_t b1) {
    asm volatile(
        "mma.sync.aligned.m16n8k16.row.col.f32.bf16.bf16.f32 "
        "{%0,%1,%2,%3}, {%4,%5,%6,%7}, {%8,%9}, {%0,%1,%2,%3};"
        : "+f"(c[0]), "+f"(c[1]), "+f"(c[2]), "+f"(c[3])
        : "r"(a[0]), "r"(a[1]), "r"(a[2]), "r"(a[3]), "r"(b0), "r"(b1));
}
__device__ __forceinline__ uint32_t swz(uint32_t off) {
    return off ^ ((off >> 3) & 0x70);
}

// smem per stage: Ahi 16K | Alo 16K | Bhi 32K | Blo 32K  (128B rows, SW128)
#define AHI 0
#define ALO 16384
#define BHI 32768
#define BLO 65536
#define STAGE 98304
#define DSMEM_BYTES (2 * STAGE + 1024)

// 6144 granules of 16B per stage -> 12 cp.async per thread at 512 threads
__device__ __forceinline__ void load_chunk(
    const __nv_bfloat16* Ahi_p, const __nv_bfloat16* Alo_p,
    const __nv_bfloat16* Bhi_p, const __nv_bfloat16* Blo_p,
    int strideA, int strideB, uint32_t buf,
    int m0, int n0, int k0, int tid) {
#pragma unroll
    for (int it = 0; it < 12; ++it) {
        int gg = tid + it * NTHREADS;            // 0..6143
        const __nv_bfloat16* src;
        uint32_t sub_off;
        int row, kc, grow, stride;
        if (gg < 2048) {                         // A: 128 rows x 8 granules x2
            int hilo = gg >> 10;
            int idx = gg & 1023;
            row = idx >> 3; kc = idx & 7;
            src = hilo ? Alo_p : Ahi_p;
            sub_off = hilo ? ALO : AHI;
            grow = m0 + row; stride = strideA;
        } else {                                 // B: 256 rows x 8 granules x2
            int r2 = gg - 2048;
            int hilo = r2 >> 11;
            int idx = r2 & 2047;
            row = idx >> 3; kc = idx & 7;
            src = hilo ? Blo_p : Bhi_p;
            sub_off = hilo ? BLO : BHI;
            grow = n0 + row; stride = strideB;
        }
        const void* gsrc = src + (size_t)grow * stride + k0 + kc * 8;
        cp16(buf + sub_off + swz((uint32_t)(row * 128 + kc * 16)), gsrc);
    }
}

// warp tile 32x64, B-fragment software pipeline (one-np lookahead):
// LDS latency exposed once per ks instead of once per np.
__device__ __forceinline__ void compute_chunk(
    uint32_t buf, int wm, int wn, int lane, float acc[2][8][4]) {
    const int arow = wm * 32 + (lane & 15);
    const int brow = wn * 64 + (lane & 15);
#pragma unroll
    for (int ks = 0; ks < 4; ++ks) {
        const int akb = ks * 32 + (lane >> 4) * 16;
        uint32_t Ah[2][4], Al[2][4];
#pragma unroll
        for (int mi = 0; mi < 2; ++mi) {
            int r = arow + mi * 16;
            ldmx4(Ah[mi][0], Ah[mi][1], Ah[mi][2], Ah[mi][3],
                  buf + AHI + swz((uint32_t)(r * 128 + akb)));
            ldmx4(Al[mi][0], Al[mi][1], Al[mi][2], Al[mi][3],
                  buf + ALO + swz((uint32_t)(r * 128 + akb)));
        }
        uint32_t Bc[8], Bn[8];
        ldmx4(Bc[0], Bc[1], Bc[2], Bc[3],
              buf + BHI + swz((uint32_t)(brow * 128 + akb)));
        ldmx4(Bc[4], Bc[5], Bc[6], Bc[7],
              buf + BLO + swz((uint32_t)(brow * 128 + akb)));
#pragma unroll
        for (int np = 0; np < 4; ++np) {
            if (np < 3) {                        // prefetch next B fragment
                int r = brow + (np + 1) * 16;
                ldmx4(Bn[0], Bn[1], Bn[2], Bn[3],
                      buf + BHI + swz((uint32_t)(r * 128 + akb)));
                ldmx4(Bn[4], Bn[5], Bn[6], Bn[7],
                      buf + BLO + swz((uint32_t)(r * 128 + akb)));
            }
#pragma unroll
            for (int mi = 0; mi < 2; ++mi) {
                mma16816(acc[mi][np * 2 + 0], Ah[mi], Bc[0], Bc[2]);
                mma16816(acc[mi][np * 2 + 1], Ah[mi], Bc[1], Bc[3]);
            }
#pragma unroll
            for (int mi = 0; mi < 2; ++mi) {
                mma16816(acc[mi][np * 2 + 0], Ah[mi], Bc[4], Bc[6]);
                mma16816(acc[mi][np * 2 + 1], Ah[mi], Bc[5], Bc[7]);
            }
#pragma unroll
            for (int mi = 0; mi < 2; ++mi) {
                mma16816(acc[mi][np * 2 + 0], Al[mi], Bc[0], Bc[2]);
                mma16816(acc[mi][np * 2 + 1], Al[mi], Bc[1], Bc[3]);
            }
            if (np < 3) {
#pragma unroll
                for (int u = 0; u < 8; ++u) Bc[u] = Bn[u];
            }
        }
    }
}

// ---------------------------------------------------------------- probe
__global__ void probe_kernel() {
    if (threadIdx.x < 32) g_probe[threadIdx.x] = (float)threadIdx.x;
}

// ---------------------------------------------------------------- prep 1
__global__ void prep1_kernel(const float* __restrict__ mag,
                             const float* __restrict__ phase) {
    int idx = blockIdx.x * blockDim.x + threadIdx.x;
    if (idx >= NN * DD) return;
    int i = idx >> 8;
    int d = idx & 255;
    float mg = mag[idx], ph = phase[idx], s, c;
    sincosf(ph, &s, &c);
    float xc = 0.25f * mg * c, xs = 0.25f * mg * s;
    __nv_bfloat16 ch = __float2bfloat16_rn(xc);
    __nv_bfloat16 sh = __float2bfloat16_rn(xs);
    size_t b = (size_t)i * KX;
    g_Xhi[b + d]      = ch;
    g_Xhi[b + DD + d] = sh;
    g_Xlo[b + d]      = __float2bfloat16_rn(xc - __bfloat162float(ch));
    g_Xlo[b + DD + d] = __float2bfloat16_rn(xs - __bfloat162float(sh));
}

// ---------------------------------------------------------------- prep 2
__global__ void prep2_kernel(const float* __restrict__ mag,
                             const float* __restrict__ phase) {
    __shared__ float sm[32][33], sp[32][33];
    int i0 = blockIdx.x * 32, d0 = blockIdx.y * 32;
    int tx = threadIdx.x, ty = threadIdx.y;
    sm[ty][tx] = mag[(size_t)(i0 + ty) * DD + d0 + tx];
    sp[ty][tx] = phase[(size_t)(i0 + ty) * DD + d0 + tx];
    __syncthreads();
    float vm = sm[tx][ty], vp = sp[tx][ty];
    __nv_bfloat16 mh = __float2bfloat16_rn(vm);
    __nv_bfloat16 ph = __float2bfloat16_rn(vp);
    size_t om = (size_t)(d0 + ty) * NN + i0 + tx;
    size_t op = (size_t)(DD + d0 + ty) * NN + i0 + tx;
    g_Wthi[om] = mh;
    g_Wthi[op] = ph;
    g_Wtlo[om] = __float2bfloat16_rn(vm - __bfloat162float(mh));
    g_Wtlo[op] = __float2bfloat16_rn(vp - __bfloat162float(ph));
}

// ---------------------------------------------------------------- SYRK
// grid (bjj=32, bi=64); keep tile iff 2*bjj+1 >= bi.
__global__ void __launch_bounds__(NTHREADS, 1)
syrk_kernel() {
    const int bjj = blockIdx.x;
    const int bi  = blockIdx.y;
    if (2 * bjj + 1 < bi) return;

    extern __shared__ char dsm[];
    uint32_t sbase = smem_u32(dsm);
    sbase = (sbase + 1023u) & ~1023u;

    const int tid = threadIdx.x;
    const int wid = tid >> 5;
    const int lane = tid & 31;
    const int wm = wid >> 2, wn = wid & 3;
    const int m0 = bi * BM;
    const int n0 = bjj * BN;

    float acc[2][8][4];
#pragma unroll
    for (int a = 0; a < 2; ++a)
#pragma unroll
        for (int b = 0; b < 8; ++b)
#pragma unroll
            for (int c = 0; c < 4; ++c) acc[a][b][c] = 0.f;

    load_chunk(g_Xhi, g_Xlo, g_Xhi, g_Xlo, KX, KX, sbase, m0, n0, 0, tid);
    CP_COMMIT();
    const int NCH = KX / BK;    // 8
    for (int c = 0; c < NCH; ++c) {
        if (c + 1 < NCH) {
            load_chunk(g_Xhi, g_Xlo, g_Xhi, g_Xlo, KX, KX,
                       sbase + ((c + 1) & 1) * STAGE, m0, n0, (c + 1) * BK, tid);
            CP_COMMIT();
            CP_WAIT1();
        } else {
            CP_WAIT0();
        }
        __syncthreads();
        compute_chunk(sbase + (c & 1) * STAGE, wm, wn, lane, acc);
        __syncthreads();
    }

    // ---- direct stores (column half c_glob kept iff >= bi)
    const int h_of_warp = wn >> 1;
    const int c_glob = 2 * bjj + h_of_warp;
    const int row0 = m0 + wm * 32 + (lane >> 2);
    const int col0 = n0 + wn * 64 + (lane & 3) * 2;
    if (c_glob >= bi) {
#pragma unroll
        for (int mi = 0; mi < 2; ++mi)
#pragma unroll
            for (int nj = 0; nj < 8; ++nj) {
                int r = row0 + mi * 16;
                int cc = col0 + nj * 8;
                float* p = g_scores + (size_t)r * NN + cc;
                *(float2*)p = make_float2(acc[mi][nj][0], acc[mi][nj][1]);
                *(float2*)(p + (size_t)8 * NN) =
                    make_float2(acc[mi][nj][2], acc[mi][nj][3]);
            }
    }

    // ---- mirror stores via smem transpose (per 128-col half)
    float* T = (float*)dsm;      // [128 cols][132]
#pragma unroll
    for (int h = 0; h < 2; ++h) {
        const int ch = 2 * bjj + h;
        if (ch > bi) {
            __syncthreads();
            if (h_of_warp == h) {
                const int lcb = (wn & 1) * 64 + (lane & 3) * 2;
                const int rl0 = wm * 32 + (lane >> 2);
#pragma unroll
                for (int mi = 0; mi < 2; ++mi)
#pragma unroll
                    for (int nj = 0; nj < 8; ++nj) {
                        int lc = lcb + nj * 8;
                        int rl = rl0 + mi * 16;
                        T[lc * 132 + rl]           = acc[mi][nj][0];
                        T[(lc + 1) * 132 + rl]     = acc[mi][nj][1];
                        T[lc * 132 + rl + 8]       = acc[mi][nj][2];
                        T[(lc + 1) * 132 + rl + 8] = acc[mi][nj][3];
                    }
            }
            __syncthreads();
            const int jj = tid >> 2;        // 0..127 (col of half -> dst row)
            const int q  = tid & 3;         // 32-float quarter
            float* dst = g_scores + (size_t)(ch * 128 + jj) * NN + m0 + q * 32;
            const float* srcT = T + jj * 132 + q * 32;
#pragma unroll
            for (int u = 0; u < 8; ++u)
                *(float4*)(dst + u * 4) = *(const float4*)(srcT + u * 4);
        }
    }
}

// ---------------------------------------------------------------- GEMM2
__global__ void __launch_bounds__(NTHREADS, 1)
gemm2_kernel() {
    extern __shared__ char dsm[];
    uint32_t sbase = smem_u32(dsm);
    sbase = (sbase + 1023u) & ~1023u;

    const int tid = threadIdx.x;
    const int wid = tid >> 5;
    const int lane = tid & 31;
    const int wm = wid >> 2, wn = wid & 3;
    const int m0 = blockIdx.y * BM;
    const int n0 = blockIdx.x * BN;
    const int sp = blockIdx.z;
    const int kbase = sp * (NN / NSPLIT);

    float acc[2][8][4];
#pragma unroll
    for (int a = 0; a < 2; ++a)
#pragma unroll
        for (int b = 0; b < 8; ++b)
#pragma unroll
            for (int c = 0; c < 4; ++c) acc[a][b][c] = 0.f;

    load_chunk(g_Ahi, g_Alo, g_Wthi, g_Wtlo, NN, NN, sbase, m0, n0, kbase, tid);
    CP_COMMIT();
    const int NCH = (NN / NSPLIT) / BK;   // 16
    for (int c = 0; c < NCH; ++c) {
        if (c + 1 < NCH) {
            load_chunk(g_Ahi, g_Alo, g_Wthi, g_Wtlo, NN, NN,
                       sbase + ((c + 1) & 1) * STAGE, m0, n0,
                       kbase + (c + 1) * BK, tid);
            CP_COMMIT();
            CP_WAIT1();
        } else {
            CP_WAIT0();
        }
        __syncthreads();
        compute_chunk(sbase + (c & 1) * STAGE, wm, wn, lane, acc);
        __syncthreads();
    }

    float* part = g_part + (size_t)sp * NN * KX;
    const int row0 = m0 + wm * 32 + (lane >> 2);
    const int col0 = n0 + wn * 64 + (lane & 3) * 2;
#pragma unroll
    for (int mi = 0; mi < 2; ++mi)
#pragma unroll
        for (int nj = 0; nj < 8; ++nj) {
            int r = row0 + mi * 16;
            int cc = col0 + nj * 8;
            float* p = part + (size_t)r * KX + cc;
            *(float2*)p = make_float2(acc[mi][nj][0], acc[mi][nj][1]);
            *(float2*)(p + (size_t)8 * KX) =
                make_float2(acc[mi][nj][2], acc[mi][nj][3]);
        }
}

// ---------------------------------------------------------------- reduce
__global__ void reduce_kernel(float* __restrict__ out) {
    int idx = blockIdx.x * blockDim.x + threadIdx.x;
    if (idx >= NN * KX / 4) return;
    const size_t stride = (size_t)NN * KX;
    float4 v = *(const float4*)(g_part + (size_t)idx * 4);
#pragma unroll
    for (int s = 1; s < NSPLIT; ++s) {
        const float4 w = *(const float4*)(g_part + s * stride + (size_t)idx * 4);
        v.x += w.x; v.y += w.y; v.z += w.z; v.w += w.w;
    }
    int r = idx >> 7;
    int c4 = idx & 127;
    int col = c4 * 4;
    size_t half = (col < DD) ? 0 : (size_t)NN * DD;
    int lc = col & (DD - 1);
    *(float4*)(out + half + (size_t)r * DD + lc) = v;
}

// ---------------------------------------------------------------- edge bias
__global__ void edge_bias_kernel(const float* __restrict__ edge_attr,
                                 const int* __restrict__ edge_index,
                                 const float* __restrict__ w1,
                                 const float* __restrict__ b1,
                                 const float* __restrict__ w2,
                                 const float* __restrict__ b2,
                                 const float* __restrict__ dist_scale) {
    __shared__ float sw1[H4], sb1[H4], sw2[H4];
    if (threadIdx.x < H4) {
        sw1[threadIdx.x] = w1[threadIdx.x];
        sb1[threadIdx.x] = b1[threadIdx.x];
        sw2[threadIdx.x] = w2[threadIdx.x];
    }
    __syncthreads();
    int e = blockIdx.x * blockDim.x + threadIdx.x;
    if (e >= EE) return;
    float a = edge_attr[e];
    float acc = b2[0];
#pragma unroll
    for (int k = 0; k < H4; ++k) {
        float x = fmaf(a, sw1[k], sb1[k]);
        float sig = 1.f / (1.f + expf(-x));
        acc = fmaf(x * sig, sw2[k], acc);
    }
    acc = fmaf(dist_scale[0], a, acc);
    int i = edge_index[e];
    int j = edge_index[EE + e];
    if ((unsigned)i < NN && (unsigned)j < NN)
        atomicAdd(&g_scores[(size_t)i * NN + j], acc);
}

// ---------------------------------------------------------------- softmax
__device__ __forceinline__ float warp_max(float v) {
#pragma unroll
    for (int o = 16; o > 0; o >>= 1) v = fmaxf(v, __shfl_xor_sync(0xffffffffu, v, o));
    return v;
}
__device__ __forceinline__ float warp_sum(float v) {
#pragma unroll
    for (int o = 16; o > 0; o >>= 1) v += __shfl_xor_sync(0xffffffffu, v, o);
    return v;
}

__global__ void softmax_kernel() {
    const int row = blockIdx.x;
    const int t = threadIdx.x;
    const float4* rp = (const float4*)&g_scores[(size_t)row * NN];
    __nv_bfloat162* rh = (__nv_bfloat162*)&g_Ahi[(size_t)row * NN];
    __nv_bfloat162* rl = (__nv_bfloat162*)&g_Alo[(size_t)row * NN];

    float4 v[8];
    float m = -3.4e38f;
#pragma unroll
    for (int i = 0; i < 8; ++i) {
        v[i] = rp[t + i * 256];
        m = fmaxf(m, fmaxf(fmaxf(v[i].x, v[i].y), fmaxf(v[i].z, v[i].w)));
    }
    __shared__ float red[8];
    int lane = t & 31, wid = t >> 5;
    m = warp_max(m);
    if (lane == 0) red[wid] = m;
    __syncthreads();
    float bm = red[0];
#pragma unroll
    for (int i = 1; i < 8; ++i) bm = fmaxf(bm, red[i]);
    __syncthreads();

    float s = 0.f;
#pragma unroll
    for (int i = 0; i < 8; ++i) {
        v[i].x = expf(v[i].x - bm);
        v[i].y = expf(v[i].y - bm);
        v[i].z = expf(v[i].z - bm);
        v[i].w = expf(v[i].w - bm);
        s += (v[i].x + v[i].y) + (v[i].z + v[i].w);
    }
    s = warp_sum(s);
    if (lane == 0) red[wid] = s;
    __syncthreads();
    float bs = 0.f;
#pragma unroll
    for (int i = 0; i < 8; ++i) bs += red[i];
    float inv = 1.f / bs;

#pragma unroll
    for (int i = 0; i < 8; ++i) {
        int idx = t + i * 256;
        float px = v[i].x * inv, py = v[i].y * inv;
        float pz = v[i].z * inv, pw = v[i].w * inv;
        __nv_bfloat16 hx = __float2bfloat16_rn(px), hy = __float2bfloat16_rn(py);
        __nv_bfloat16 hz = __float2bfloat16_rn(pz), hw = __float2bfloat16_rn(pw);
        __nv_bfloat162 h0, h1, l0, l1;
        h0.x = hx; h0.y = hy; h1.x = hz; h1.y = hw;
        l0.x = __float2bfloat16_rn(px - __bfloat162float(hx));
        l0.y = __float2bfloat16_rn(py - __bfloat162float(hy));
        l1.x = __float2bfloat16_rn(pz - __bfloat162float(hz));
        l1.y = __float2bfloat16_rn(pw - __bfloat162float(hw));
        rh[2 * idx]     = h0;
        rh[2 * idx + 1] = h1;
        rl[2 * idx]     = l0;
        rl[2 * idx + 1] = l1;
    }
}

// ---------------------------------------------------------------- launch
extern "C" void kernel_launch(void* const* d_in, const int* in_sizes, int n_in,
                              void* d_out, int out_size) {
    const float* mag        = (const float*)d_in[0];
    const float* phase      = (const float*)d_in[1];
    const float* edge_attr  = (const float*)d_in[2];
    const int*   edge_index = (const int*)d_in[3];
    const float* w1         = (const float*)d_in[4];
    const float* b1         = (const float*)d_in[5];
    const float* w2         = (const float*)d_in[6];
    const float* b2         = (const float*)d_in[7];
    const float* dist_scale = (const float*)d_in[8];
    float*       out        = (float*)d_out;

    cudaFuncSetAttribute(syrk_kernel,
                         cudaFuncAttributeMaxDynamicSharedMemorySize, DSMEM_BYTES);
    cudaFuncSetAttribute(gemm2_kernel,
                         cudaFuncAttributeMaxDynamicSharedMemorySize, DSMEM_BYTES);

    prep1_kernel<<<(NN * DD + 255) / 256, 256>>>(mag, phase);          // #1
    prep2_kernel<<<dim3(NN / 32, DD / 32), dim3(32, 32)>>>(mag, phase); // #2
    probe_kernel<<<1, 32>>>();                                         // #3
    syrk_kernel<<<dim3(NN / BN, NN / BM), NTHREADS, DSMEM_BYTES>>>();  // #4 -> profiled
    edge_bias_kernel<<<(EE + 255) / 256, 256>>>(edge_attr, edge_index,
                                                w1, b1, w2, b2, dist_scale);
    softmax_kernel<<<NN, 256>>>();
    gemm2_kernel<<<dim3(KX / BN, NN / BM, NSPLIT), NTHREADS, DSMEM_BYTES>>>();
    reduce_kernel<<<(NN * KX / 4 + 255) / 256, 256>>>(out);
}

// round 11
// speedup vs baseline: 1.5317x; 1.5317x over previous
#include <cuda_runtime.h>
#include <cuda_fp16.h>
#include <math.h>
#include <stdint.h>

// ---------------------------------------------------------------- constants
#define NN 8192
#define DD 256
#define KX 512
#define EE 262144
#define H4 64
#define BM 128           // CTA tile M
#define BN 256           // CTA tile N
#define BK 64            // K chunk (fp16 elems)
#define NTHREADS 512     // 16 warps, warp tile 32x64
#define NSPLIT 8         // split-K for gemm2
#define ASCALE 256.0f    // attn stored *256 in fp16 (avoids subnormals)

// ---------------------------------------------------------------- scratch
__device__ float  g_scores[(size_t)NN * NN];
__device__ __half g_Xh[(size_t)NN * KX];     // [mc|ms]/4, single fp16
__device__ __half g_Wth[(size_t)KX * NN];    // W^T hi (fp16 split)
__device__ __half g_Wtl[(size_t)KX * NN];    // W^T lo
__device__ __half g_Ah[(size_t)NN * NN];     // attn * 256, single fp16
__device__ float  g_part[(size_t)NSPLIT * NN * KX];
__device__ float  g_probe[32];

// ---------------------------------------------------------------- PTX utils
__device__ __forceinline__ uint32_t smem_u32(const void* p) {
    uint32_t a;
    asm("{ .reg .u64 t; cvta.to.shared.u64 t, %1; cvt.u32.u64 %0, t; }"
        : "=r"(a) : "l"(p));
    return a;
}
__device__ __forceinline__ void cp16(uint32_t dst, const void* src) {
    asm volatile("cp.async.cg.shared.global [%0], [%1], 16;"
                 :: "r"(dst), "l"(src) : "memory");
}
#define CP_COMMIT() asm volatile("cp.async.commit_group;" ::: "memory")
#define CP_WAIT1()  asm volatile("cp.async.wait_group 1;" ::: "memory")
#define CP_WAIT0()  asm volatile("cp.async.wait_group 0;" ::: "memory")

__device__ __forceinline__ void ldmx4(uint32_t& r0, uint32_t& r1,
                                      uint32_t& r2, uint32_t& r3, uint32_t a) {
    asm volatile("ldmatrix.sync.aligned.m8n8.x4.shared.b16 {%0,%1,%2,%3}, [%4];"
                 : "=r"(r0), "=r"(r1), "=r"(r2), "=r"(r3) : "r"(a));
}
__device__ __forceinline__ void mma16816(float* c, const uint32_t* a,
                                         uint32_t b0, uint32_t b1) {
    asm volatile(
        "mma.sync.aligned.m16n8k16.row.col.f32.f16.f16.f32 "
        "{%0,%1,%2,%3}, {%4,%5,%6,%7}, {%8,%9}, {%0,%1,%2,%3};"
        : "+f"(c[0]), "+f"(c[1]), "+f"(c[2]), "+f"(c[3])
        : "r"(a[0]), "r"(a[1]), "r"(a[2]), "r"(a[3]), "r"(b0), "r"(b1));
}
__device__ __forceinline__ uint32_t swz(uint32_t off) {
    return off ^ ((off >> 3) & 0x70);
}

// ------------- SYRK smem: A 16K @0 | B 32K @16384 ; 2 stages
#define S_B 16384
#define STAGE_S 49152
#define DSMEM_S (2 * STAGE_S + 1024)
// ------------- GEMM2 smem: A 16K @0 | Bh 32K @16384 | Bl 32K @49152 ; 2 stages
#define G_BH 16384
#define G_BL 49152
#define STAGE_G 81920
#define DSMEM_G (2 * STAGE_G + 1024)

// SYRK loads: A 1024 + B 2048 granules = 3072 -> 6 per thread
__device__ __forceinline__ void load_chunk_syrk(uint32_t buf, int m0, int n0,
                                                int k0, int tid) {
#pragma unroll
    for (int it = 0; it < 6; ++it) {
        int gg = tid + it * NTHREADS;          // 0..3071
        int isB = gg >= 1024;
        int idx = isB ? gg - 1024 : gg;
        int row = idx >> 3;
        int kc = idx & 7;
        int grow = (isB ? n0 : m0) + row;
        cp16(buf + (isB ? S_B : 0) + swz((uint32_t)(row * 128 + kc * 16)),
             g_Xh + (size_t)grow * KX + k0 + kc * 8);
    }
}

// GEMM2 loads: A 1024 + Bh 2048 + Bl 2048 = 5120 -> 10 per thread
__device__ __forceinline__ void load_chunk_g2(uint32_t buf, int m0, int n0,
                                              int k0, int tid) {
#pragma unroll
    for (int it = 0; it < 10; ++it) {
        int gg = tid + it * NTHREADS;          // 0..5119
        const __half* src;
        uint32_t off;
        int row, kc, grow, stride;
        if (gg < 1024) {                       // A (attn)
            row = gg >> 3; kc = gg & 7;
            src = g_Ah; off = 0; grow = m0 + row; stride = NN;
        } else if (gg < 3072) {                // Bh
            int idx = gg - 1024;
            row = idx >> 3; kc = idx & 7;
            src = g_Wth; off = G_BH; grow = n0 + row; stride = NN;
        } else {                               // Bl
            int idx = gg - 3072;
            row = idx >> 3; kc = idx & 7;
            src = g_Wtl; off = G_BL; grow = n0 + row; stride = NN;
        }
        cp16(buf + off + swz((uint32_t)(row * 128 + kc * 16)),
             src + (size_t)grow * stride + k0 + kc * 8);
    }
}

// SYRK compute: single pass, 64 MMA / chunk / warp
__device__ __forceinline__ void compute_chunk_syrk(
    uint32_t buf, int wm, int wn, int lane, float acc[2][8][4]) {
    const int arow = wm * 32 + (lane & 15);
    const int brow = wn * 64 + (lane & 15);
#pragma unroll
    for (int ks = 0; ks < 4; ++ks) {
        const int akb = ks * 32 + (lane >> 4) * 16;
        uint32_t A[2][4];
#pragma unroll
        for (int mi = 0; mi < 2; ++mi)
            ldmx4(A[mi][0], A[mi][1], A[mi][2], A[mi][3],
                  buf + swz((uint32_t)((arow + mi * 16) * 128 + akb)));
#pragma unroll
        for (int np = 0; np < 4; ++np) {
            uint32_t B[4];
            ldmx4(B[0], B[1], B[2], B[3],
                  buf + S_B + swz((uint32_t)((brow + np * 16) * 128 + akb)));
#pragma unroll
            for (int mi = 0; mi < 2; ++mi) {
                mma16816(acc[mi][np * 2 + 0], A[mi], B[0], B[2]);
                mma16816(acc[mi][np * 2 + 1], A[mi], B[1], B[3]);
            }
        }
    }
}

// GEMM2 compute: A single, B split -> 2 passes, 128 MMA / chunk / warp
__device__ __forceinline__ void compute_chunk_g2(
    uint32_t buf, int wm, int wn, int lane, float acc[2][8][4]) {
    const int arow = wm * 32 + (lane & 15);
    const int brow = wn * 64 + (lane & 15);
#pragma unroll
    for (int ks = 0; ks < 4; ++ks) {
        const int akb = ks * 32 + (lane >> 4) * 16;
        uint32_t A[2][4];
#pragma unroll
        for (int mi = 0; mi < 2; ++mi)
            ldmx4(A[mi][0], A[mi][1], A[mi][2], A[mi][3],
                  buf + swz((uint32_t)((arow + mi * 16) * 128 + akb)));
#pragma unroll
        for (int np = 0; np < 4; ++np) {
            uint32_t Bh[4], Bl[4];
            ldmx4(Bh[0], Bh[1], Bh[2], Bh[3],
                  buf + G_BH + swz((uint32_t)((brow + np * 16) * 128 + akb)));
            ldmx4(Bl[0], Bl[1], Bl[2], Bl[3],
                  buf + G_BL + swz((uint32_t)((brow + np * 16) * 128 + akb)));
#pragma unroll
            for (int mi = 0; mi < 2; ++mi) {
                mma16816(acc[mi][np * 2 + 0], A[mi], Bh[0], Bh[2]);
                mma16816(acc[mi][np * 2 + 1], A[mi], Bh[1], Bh[3]);
            }
#pragma unroll
            for (int mi = 0; mi < 2; ++mi) {
                mma16816(acc[mi][np * 2 + 0], A[mi], Bl[0], Bl[2]);
                mma16816(acc[mi][np * 2 + 1], A[mi], Bl[1], Bl[3]);
            }
        }
    }
}

// ---------------------------------------------------------------- probe
__global__ void probe_kernel() {
    if (threadIdx.x < 32) g_probe[threadIdx.x] = (float)threadIdx.x;
}

// ---------------------------------------------------------------- prep 1
// X = fp16(mag*cos(phase)/4 | mag*sin(phase)/4)
__global__ void prep1_kernel(const float* __restrict__ mag,
                             const float* __restrict__ phase) {
    int idx = blockIdx.x * blockDim.x + threadIdx.x;
    if (idx >= NN * DD) return;
    int i = idx >> 8;
    int d = idx & 255;
    float mg = mag[idx], ph = phase[idx], s, c;
    sincosf(ph, &s, &c);
    size_t b = (size_t)i * KX;
    g_Xh[b + d]      = __float2half_rn(0.25f * mg * c);
    g_Xh[b + DD + d] = __float2half_rn(0.25f * mg * s);
}

// ---------------------------------------------------------------- prep 2
// W^T fp16 split: Wt[d][i]=mag[i][d], Wt[256+d][i]=phase[i][d]
__global__ void prep2_kernel(const float* __restrict__ mag,
                             const float* __restrict__ phase) {
    __shared__ float sm[32][33], sp[32][33];
    int i0 = blockIdx.x * 32, d0 = blockIdx.y * 32;
    int tx = threadIdx.x, ty = threadIdx.y;
    sm[ty][tx] = mag[(size_t)(i0 + ty) * DD + d0 + tx];
    sp[ty][tx] = phase[(size_t)(i0 + ty) * DD + d0 + tx];
    __syncthreads();
    float vm = sm[tx][ty], vp = sp[tx][ty];
    __half mh = __float2half_rn(vm);
    __half ph = __float2half_rn(vp);
    size_t om = (size_t)(d0 + ty) * NN + i0 + tx;
    size_t op = (size_t)(DD + d0 + ty) * NN + i0 + tx;
    g_Wth[om] = mh;
    g_Wth[op] = ph;
    g_Wtl[om] = __float2half_rn(vm - __half2float(mh));
    g_Wtl[op] = __float2half_rn(vp - __half2float(ph));
}

// ---------------------------------------------------------------- SYRK
// grid (bjj=32, bi=64); keep tile iff 2*bjj+1 >= bi.
__global__ void __launch_bounds__(NTHREADS, 1)
syrk_kernel() {
    const int bjj = blockIdx.x;
    const int bi  = blockIdx.y;
    if (2 * bjj + 1 < bi) return;

    extern __shared__ char dsm[];
    uint32_t sbase = smem_u32(dsm);
    sbase = (sbase + 1023u) & ~1023u;

    const int tid = threadIdx.x;
    const int wid = tid >> 5;
    const int lane = tid & 31;
    const int wm = wid >> 2, wn = wid & 3;
    const int m0 = bi * BM;
    const int n0 = bjj * BN;

    float acc[2][8][4];
#pragma unroll
    for (int a = 0; a < 2; ++a)
#pragma unroll
        for (int b = 0; b < 8; ++b)
#pragma unroll
            for (int c = 0; c < 4; ++c) acc[a][b][c] = 0.f;

    load_chunk_syrk(sbase, m0, n0, 0, tid);
    CP_COMMIT();
    const int NCH = KX / BK;    // 8
    for (int c = 0; c < NCH; ++c) {
        if (c + 1 < NCH) {
            load_chunk_syrk(sbase + ((c + 1) & 1) * STAGE_S, m0, n0,
                            (c + 1) * BK, tid);
            CP_COMMIT();
            CP_WAIT1();
        } else {
            CP_WAIT0();
        }
        __syncthreads();
        compute_chunk_syrk(sbase + (c & 1) * STAGE_S, wm, wn, lane, acc);
        __syncthreads();
    }

    // ---- direct stores (column half c_glob kept iff >= bi)
    const int h_of_warp = wn >> 1;
    const int c_glob = 2 * bjj + h_of_warp;
    const int row0 = m0 + wm * 32 + (lane >> 2);
    const int col0 = n0 + wn * 64 + (lane & 3) * 2;
    if (c_glob >= bi) {
#pragma unroll
        for (int mi = 0; mi < 2; ++mi)
#pragma unroll
            for (int nj = 0; nj < 8; ++nj) {
                int r = row0 + mi * 16;
                int cc = col0 + nj * 8;
                float* p = g_scores + (size_t)r * NN + cc;
                *(float2*)p = make_float2(acc[mi][nj][0], acc[mi][nj][1]);
                *(float2*)(p + (size_t)8 * NN) =
                    make_float2(acc[mi][nj][2], acc[mi][nj][3]);
            }
    }

    // ---- mirror stores via smem transpose (per 128-col half)
    float* T = (float*)dsm;      // [128 cols][132]
#pragma unroll
    for (int h = 0; h < 2; ++h) {
        const int ch = 2 * bjj + h;
        if (ch > bi) {
            __syncthreads();
            if (h_of_warp == h) {
                const int lcb = (wn & 1) * 64 + (lane & 3) * 2;
                const int rl0 = wm * 32 + (lane >> 2);
#pragma unroll
                for (int mi = 0; mi < 2; ++mi)
#pragma unroll
                    for (int nj = 0; nj < 8; ++nj) {
                        int lc = lcb + nj * 8;
                        int rl = rl0 + mi * 16;
                        T[lc * 132 + rl]           = acc[mi][nj][0];
                        T[(lc + 1) * 132 + rl]     = acc[mi][nj][1];
                        T[lc * 132 + rl + 8]       = acc[mi][nj][2];
                        T[(lc + 1) * 132 + rl + 8] = acc[mi][nj][3];
                    }
            }
            __syncthreads();
            const int jj = tid >> 2;
            const int q  = tid & 3;
            float* dst = g_scores + (size_t)(ch * 128 + jj) * NN + m0 + q * 32;
            const float* srcT = T + jj * 132 + q * 32;
#pragma unroll
            for (int u = 0; u < 8; ++u)
                *(float4*)(dst + u * 4) = *(const float4*)(srcT + u * 4);
        }
    }
}

// ---------------------------------------------------------------- GEMM2
__global__ void __launch_bounds__(NTHREADS, 1)
gemm2_kernel() {
    extern __shared__ char dsm[];
    uint32_t sbase = smem_u32(dsm);
    sbase = (sbase + 1023u) & ~1023u;

    const int tid = threadIdx.x;
    const int wid = tid >> 5;
    const int lane = tid & 31;
    const int wm = wid >> 2, wn = wid & 3;
    const int m0 = blockIdx.y * BM;
    const int n0 = blockIdx.x * BN;
    const int sp = blockIdx.z;
    const int kbase = sp * (NN / NSPLIT);

    float acc[2][8][4];
#pragma unroll
    for (int a = 0; a < 2; ++a)
#pragma unroll
        for (int b = 0; b < 8; ++b)
#pragma unroll
            for (int c = 0; c < 4; ++c) acc[a][b][c] = 0.f;

    load_chunk_g2(sbase, m0, n0, kbase, tid);
    CP_COMMIT();
    const int NCH = (NN / NSPLIT) / BK;   // 16
    for (int c = 0; c < NCH; ++c) {
        if (c + 1 < NCH) {
            load_chunk_g2(sbase + ((c + 1) & 1) * STAGE_G, m0, n0,
                          kbase + (c + 1) * BK, tid);
            CP_COMMIT();
            CP_WAIT1();
        } else {
            CP_WAIT0();
        }
        __syncthreads();
        compute_chunk_g2(sbase + (c & 1) * STAGE_G, wm, wn, lane, acc);
        __syncthreads();
    }

    float* part = g_part + (size_t)sp * NN * KX;
    const int row0 = m0 + wm * 32 + (lane >> 2);
    const int col0 = n0 + wn * 64 + (lane & 3) * 2;
#pragma unroll
    for (int mi = 0; mi < 2; ++mi)
#pragma unroll
        for (int nj = 0; nj < 8; ++nj) {
            int r = row0 + mi * 16;
            int cc = col0 + nj * 8;
            float* p = part + (size_t)r * KX + cc;
            *(float2*)p = make_float2(acc[mi][nj][0], acc[mi][nj][1]);
            *(float2*)(p + (size_t)8 * KX) =
                make_float2(acc[mi][nj][2], acc[mi][nj][3]);
        }
}

// ---------------------------------------------------------------- reduce
// sums split-K partials and divides out the ASCALE attn scaling
__global__ void reduce_kernel(float* __restrict__ out) {
    int idx = blockIdx.x * blockDim.x + threadIdx.x;
    if (idx >= NN * KX / 4) return;
    const size_t stride = (size_t)NN * KX;
    float4 v = *(const float4*)(g_part + (size_t)idx * 4);
#pragma unroll
    for (int s = 1; s < NSPLIT; ++s) {
        const float4 w = *(const float4*)(g_part + s * stride + (size_t)idx * 4);
        v.x += w.x; v.y += w.y; v.z += w.z; v.w += w.w;
    }
    const float inv = 1.0f / ASCALE;
    v.x *= inv; v.y *= inv; v.z *= inv; v.w *= inv;
    int r = idx >> 7;
    int c4 = idx & 127;
    int col = c4 * 4;
    size_t half = (col < DD) ? 0 : (size_t)NN * DD;
    int lc = col & (DD - 1);
    *(float4*)(out + half + (size_t)r * DD + lc) = v;
}

// ---------------------------------------------------------------- edge bias
__global__ void edge_bias_kernel(const float* __restrict__ edge_attr,
                                 const int* __restrict__ edge_index,
                                 const float* __restrict__ w1,
                                 const float* __restrict__ b1,
                                 const float* __restrict__ w2,
                                 const float* __restrict__ b2,
                                 const float* __restrict__ dist_scale) {
    __shared__ float sw1[H4], sb1[H4], sw2[H4];
    if (threadIdx.x < H4) {
        sw1[threadIdx.x] = w1[threadIdx.x];
        sb1[threadIdx.x] = b1[threadIdx.x];
        sw2[threadIdx.x] = w2[threadIdx.x];
    }
    __syncthreads();
    int e = blockIdx.x * blockDim.x + threadIdx.x;
    if (e >= EE) return;
    float a = edge_attr[e];
    float acc = b2[0];
#pragma unroll
    for (int k = 0; k < H4; ++k) {
        float x = fmaf(a, sw1[k], sb1[k]);
        float sig = 1.f / (1.f + expf(-x));
        acc = fmaf(x * sig, sw2[k], acc);
    }
    acc = fmaf(dist_scale[0], a, acc);
    int i = edge_index[e];
    int j = edge_index[EE + e];
    if ((unsigned)i < NN && (unsigned)j < NN)
        atomicAdd(&g_scores[(size_t)i * NN + j], acc);
}

// ---------------------------------------------------------------- softmax
// reads fp32 logits, writes attn * 256 as single fp16
__device__ __forceinline__ float warp_max(float v) {
#pragma unroll
    for (int o = 16; o > 0; o >>= 1) v = fmaxf(v, __shfl_xor_sync(0xffffffffu, v, o));
    return v;
}
__device__ __forceinline__ float warp_sum(float v) {
#pragma unroll
    for (int o = 16; o > 0; o >>= 1) v += __shfl_xor_sync(0xffffffffu, v, o);
    return v;
}

__global__ void softmax_kernel() {
    const int row = blockIdx.x;
    const int t = threadIdx.x;
    const float4* rp = (const float4*)&g_scores[(size_t)row * NN];
    __half2* rh = (__half2*)&g_Ah[(size_t)row * NN];

    float4 v[8];
    float m = -3.4e38f;
#pragma unroll
    for (int i = 0; i < 8; ++i) {
        v[i] = rp[t + i * 256];
        m = fmaxf(m, fmaxf(fmaxf(v[i].x, v[i].y), fmaxf(v[i].z, v[i].w)));
    }
    __shared__ float red[8];
    int lane = t & 31, wid = t >> 5;
    m = warp_max(m);
    if (lane == 0) red[wid] = m;
    __syncthreads();
    float bm = red[0];
#pragma unroll
    for (int i = 1; i < 8; ++i) bm = fmaxf(bm, red[i]);
    __syncthreads();

    float s = 0.f;
#pragma unroll
    for (int i = 0; i < 8; ++i) {
        v[i].x = expf(v[i].x - bm);
        v[i].y = expf(v[i].y - bm);
        v[i].z = expf(v[i].z - bm);
        v[i].w = expf(v[i].w - bm);
        s += (v[i].x + v[i].y) + (v[i].z + v[i].w);
    }
    s = warp_sum(s);
    if (lane == 0) red[wid] = s;
    __syncthreads();
    float bs = 0.f;
#pragma unroll
    for (int i = 0; i < 8; ++i) bs += red[i];
    const float invs = ASCALE / bs;

#pragma unroll
    for (int i = 0; i < 8; ++i) {
        int idx = t + i * 256;
        rh[2 * idx]     = __floats2half2_rn(v[i].x * invs, v[i].y * invs);
        rh[2 * idx + 1] = __floats2half2_rn(v[i].z * invs, v[i].w * invs);
    }
}

// ---------------------------------------------------------------- launch
extern "C" void kernel_launch(void* const* d_in, const int* in_sizes, int n_in,
                              void* d_out, int out_size) {
    const float* mag        = (const float*)d_in[0];
    const float* phase      = (const float*)d_in[1];
    const float* edge_attr  = (const float*)d_in[2];
    const int*   edge_index = (const int*)d_in[3];
    const float* w1         = (const float*)d_in[4];
    const float* b1         = (const float*)d_in[5];
    const float* w2         = (const float*)d_in[6];
    const float* b2         = (const float*)d_in[7];
    const float* dist_scale = (const float*)d_in[8];
    float*       out        = (float*)d_out;

    cudaFuncSetAttribute(syrk_kernel,
                         cudaFuncAttributeMaxDynamicSharedMemorySize, DSMEM_S);
    cudaFuncSetAttribute(gemm2_kernel,
                         cudaFuncAttributeMaxDynamicSharedMemorySize, DSMEM_G);

    prep1_kernel<<<(NN * DD + 255) / 256, 256>>>(mag, phase);          // #1
    prep2_kernel<<<dim3(NN / 32, DD / 32), dim3(32, 32)>>>(mag, phase); // #2
    probe_kernel<<<1, 32>>>();                                         // #3
    syrk_kernel<<<dim3(NN / BN, NN / BM), NTHREADS, DSMEM_S>>>();      // #4 -> profiled
    edge_bias_kernel<<<(EE + 255) / 256, 256>>>(edge_attr, edge_index,
                                                w1, b1, w2, b2, dist_scale);
    softmax_kernel<<<NN, 256>>>();
    gemm2_kernel<<<dim3(KX / BN, NN / BM, NSPLIT), NTHREADS, DSMEM_G>>>();
    reduce_kernel<<<(NN * KX / 4 + 255) / 256, 256>>>(out);
}

// round 12
// speedup vs baseline: 2.0477x; 1.3369x over previous
#include <cuda_runtime.h>
#include <cuda_fp16.h>
#include <math.h>
#include <stdint.h>

// ---------------------------------------------------------------- constants
#define NN 8192
#define DD 256
#define KX 512
#define EE 262144
#define H4 64
#define BM 128           // CTA tile M
#define BN 256           // CTA tile N
#define BK 64            // K chunk (fp16 elems)
#define NTHREADS 512     // 16 warps, warp tile 32x64
#define NSPLIT 8         // split-K for gemm2
#define ASCALE 256.0f    // attn stored *256 in fp16 (avoids subnormals)

// ---------------------------------------------------------------- scratch
__device__ float  g_scores[(size_t)NN * NN];
__device__ __half g_Xh[(size_t)NN * KX];     // [mc|ms]/4, single fp16
__device__ __half g_Wth[(size_t)KX * NN];    // W^T, single fp16
__device__ __half g_Ah[(size_t)NN * NN];     // attn * 256, single fp16
__device__ float  g_part[(size_t)NSPLIT * NN * KX];
__device__ float  g_probe[32];

// ---------------------------------------------------------------- PTX utils
__device__ __forceinline__ uint32_t smem_u32(const void* p) {
    uint32_t a;
    asm("{ .reg .u64 t; cvta.to.shared.u64 t, %1; cvt.u32.u64 %0, t; }"
        : "=r"(a) : "l"(p));
    return a;
}
__device__ __forceinline__ void cp16(uint32_t dst, const void* src) {
    asm volatile("cp.async.cg.shared.global [%0], [%1], 16;"
                 :: "r"(dst), "l"(src) : "memory");
}
#define CP_COMMIT() asm volatile("cp.async.commit_group;" ::: "memory")
#define CP_WAIT1()  asm volatile("cp.async.wait_group 1;" ::: "memory")
#define CP_WAIT0()  asm volatile("cp.async.wait_group 0;" ::: "memory")

__device__ __forceinline__ void ldmx4(uint32_t& r0, uint32_t& r1,
                                      uint32_t& r2, uint32_t& r3, uint32_t a) {
    asm volatile("ldmatrix.sync.aligned.m8n8.x4.shared.b16 {%0,%1,%2,%3}, [%4];"
                 : "=r"(r0), "=r"(r1), "=r"(r2), "=r"(r3) : "r"(a));
}
__device__ __forceinline__ void mma16816(float* c, const uint32_t* a,
                                         uint32_t b0, uint32_t b1) {
    asm volatile(
        "mma.sync.aligned.m16n8k16.row.col.f32.f16.f16.f32 "
        "{%0,%1,%2,%3}, {%4,%5,%6,%7}, {%8,%9}, {%0,%1,%2,%3};"
        : "+f"(c[0]), "+f"(c[1]), "+f"(c[2]), "+f"(c[3])
        : "r"(a[0]), "r"(a[1]), "r"(a[2]), "r"(a[3]), "r"(b0), "r"(b1));
}
__device__ __forceinline__ uint32_t swz(uint32_t off) {
    return off ^ ((off >> 3) & 0x70);
}

// smem per stage: A 16K @0 | B 32K @16384 ; 2 stages (both kernels)
#define S_B 16384
#define STAGE 49152
#define DSMEM_BYTES (2 * STAGE + 1024)

// loads: A 1024 + B 2048 granules = 3072 -> 6 per thread
__device__ __forceinline__ void load_chunk(
    const __half* Ap, const __half* Bp, int strideA, int strideB,
    uint32_t buf, int m0, int n0, int k0, int tid) {
#pragma unroll
    for (int it = 0; it < 6; ++it) {
        int gg = tid + it * NTHREADS;          // 0..3071
        int isB = gg >= 1024;
        int idx = isB ? gg - 1024 : gg;
        int row = idx >> 3;
        int kc = idx & 7;
        const __half* src = isB ? Bp : Ap;
        int grow = (isB ? n0 : m0) + row;
        int stride = isB ? strideB : strideA;
        cp16(buf + (isB ? S_B : 0) + swz((uint32_t)(row * 128 + kc * 16)),
             src + (size_t)grow * stride + k0 + kc * 8);
    }
}

// single-pass compute: warp tile 32x64, 64 MMA / chunk / warp
__device__ __forceinline__ void compute_chunk(
    uint32_t buf, int wm, int wn, int lane, float acc[2][8][4]) {
    const int arow = wm * 32 + (lane & 15);
    const int brow = wn * 64 + (lane & 15);
#pragma unroll
    for (int ks = 0; ks < 4; ++ks) {
        const int akb = ks * 32 + (lane >> 4) * 16;
        uint32_t A[2][4];
#pragma unroll
        for (int mi = 0; mi < 2; ++mi)
            ldmx4(A[mi][0], A[mi][1], A[mi][2], A[mi][3],
                  buf + swz((uint32_t)((arow + mi * 16) * 128 + akb)));
#pragma unroll
        for (int np = 0; np < 4; ++np) {
            uint32_t B[4];
            ldmx4(B[0], B[1], B[2], B[3],
                  buf + S_B + swz((uint32_t)((brow + np * 16) * 128 + akb)));
#pragma unroll
            for (int mi = 0; mi < 2; ++mi) {
                mma16816(acc[mi][np * 2 + 0], A[mi], B[0], B[2]);
                mma16816(acc[mi][np * 2 + 1], A[mi], B[1], B[3]);
            }
        }
    }
}

// ---------------------------------------------------------------- probe
__global__ void probe_kernel() {
    if (threadIdx.x < 32) g_probe[threadIdx.x] = (float)threadIdx.x;
}

// ---------------------------------------------------------------- prep 1
__global__ void prep1_kernel(const float* __restrict__ mag,
                             const float* __restrict__ phase) {
    int idx = blockIdx.x * blockDim.x + threadIdx.x;
    if (idx >= NN * DD) return;
    int i = idx >> 8;
    int d = idx & 255;
    float mg = mag[idx], ph = phase[idx], s, c;
    sincosf(ph, &s, &c);
    size_t b = (size_t)i * KX;
    g_Xh[b + d]      = __float2half_rn(0.25f * mg * c);
    g_Xh[b + DD + d] = __float2half_rn(0.25f * mg * s);
}

// ---------------------------------------------------------------- prep 2
// W^T single fp16: Wt[d][i]=mag[i][d], Wt[256+d][i]=phase[i][d]
__global__ void prep2_kernel(const float* __restrict__ mag,
                             const float* __restrict__ phase) {
    __shared__ float sm[32][33], sp[32][33];
    int i0 = blockIdx.x * 32, d0 = blockIdx.y * 32;
    int tx = threadIdx.x, ty = threadIdx.y;
    sm[ty][tx] = mag[(size_t)(i0 + ty) * DD + d0 + tx];
    sp[ty][tx] = phase[(size_t)(i0 + ty) * DD + d0 + tx];
    __syncthreads();
    g_Wth[(size_t)(d0 + ty) * NN + i0 + tx]      = __float2half_rn(sm[tx][ty]);
    g_Wth[(size_t)(DD + d0 + ty) * NN + i0 + tx] = __float2half_rn(sp[tx][ty]);
}

// ---------------------------------------------------------------- SYRK
// grid (bjj=32, bi=64); keep tile iff 2*bjj+1 >= bi.
__global__ void __launch_bounds__(NTHREADS, 1)
syrk_kernel() {
    const int bjj = blockIdx.x;
    const int bi  = blockIdx.y;
    if (2 * bjj + 1 < bi) return;

    extern __shared__ char dsm[];
    uint32_t sbase = smem_u32(dsm);
    sbase = (sbase + 1023u) & ~1023u;

    const int tid = threadIdx.x;
    const int wid = tid >> 5;
    const int lane = tid & 31;
    const int wm = wid >> 2, wn = wid & 3;
    const int m0 = bi * BM;
    const int n0 = bjj * BN;

    float acc[2][8][4];
#pragma unroll
    for (int a = 0; a < 2; ++a)
#pragma unroll
        for (int b = 0; b < 8; ++b)
#pragma unroll
            for (int c = 0; c < 4; ++c) acc[a][b][c] = 0.f;

    load_chunk(g_Xh, g_Xh, KX, KX, sbase, m0, n0, 0, tid);
    CP_COMMIT();
    const int NCH = KX / BK;    // 8
    for (int c = 0; c < NCH; ++c) {
        if (c + 1 < NCH) {
            load_chunk(g_Xh, g_Xh, KX, KX, sbase + ((c + 1) & 1) * STAGE,
                       m0, n0, (c + 1) * BK, tid);
            CP_COMMIT();
            CP_WAIT1();
        } else {
            CP_WAIT0();
        }
        __syncthreads();
        compute_chunk(sbase + (c & 1) * STAGE, wm, wn, lane, acc);
        __syncthreads();
    }

    // ---- direct stores (column half c_glob kept iff >= bi)
    const int h_of_warp = wn >> 1;
    const int c_glob = 2 * bjj + h_of_warp;
    const int row0 = m0 + wm * 32 + (lane >> 2);
    const int col0 = n0 + wn * 64 + (lane & 3) * 2;
    if (c_glob >= bi) {
#pragma unroll
        for (int mi = 0; mi < 2; ++mi)
#pragma unroll
            for (int nj = 0; nj < 8; ++nj) {
                int r = row0 + mi * 16;
                int cc = col0 + nj * 8;
                float* p = g_scores + (size_t)r * NN + cc;
                *(float2*)p = make_float2(acc[mi][nj][0], acc[mi][nj][1]);
                *(float2*)(p + (size_t)8 * NN) =
                    make_float2(acc[mi][nj][2], acc[mi][nj][3]);
            }
    }

    // ---- mirror stores via smem transpose (per 128-col half)
    float* T = (float*)dsm;      // [128 cols][132]
#pragma unroll
    for (int h = 0; h < 2; ++h) {
        const int ch = 2 * bjj + h;
        if (ch > bi) {
            __syncthreads();
            if (h_of_warp == h) {
                const int lcb = (wn & 1) * 64 + (lane & 3) * 2;
                const int rl0 = wm * 32 + (lane >> 2);
#pragma unroll
                for (int mi = 0; mi < 2; ++mi)
#pragma unroll
                    for (int nj = 0; nj < 8; ++nj) {
                        int lc = lcb + nj * 8;
                        int rl = rl0 + mi * 16;
                        T[lc * 132 + rl]           = acc[mi][nj][0];
                        T[(lc + 1) * 132 + rl]     = acc[mi][nj][1];
                        T[lc * 132 + rl + 8]       = acc[mi][nj][2];
                        T[(lc + 1) * 132 + rl + 8] = acc[mi][nj][3];
                    }
            }
            __syncthreads();
            const int jj = tid >> 2;
            const int q  = tid & 3;
            float* dst = g_scores + (size_t)(ch * 128 + jj) * NN + m0 + q * 32;
            const float* srcT = T + jj * 132 + q * 32;
#pragma unroll
            for (int u = 0; u < 8; ++u)
                *(float4*)(dst + u * 4) = *(const float4*)(srcT + u * 4);
        }
    }
}

// ---------------------------------------------------------------- GEMM2
// single-pass: partial[split] = (attn*256 fp16) @ (W^T fp16)
__global__ void __launch_bounds__(NTHREADS, 1)
gemm2_kernel() {
    extern __shared__ char dsm[];
    uint32_t sbase = smem_u32(dsm);
    sbase = (sbase + 1023u) & ~1023u;

    const int tid = threadIdx.x;
    const int wid = tid >> 5;
    const int lane = tid & 31;
    const int wm = wid >> 2, wn = wid & 3;
    const int m0 = blockIdx.y * BM;
    const int n0 = blockIdx.x * BN;
    const int sp = blockIdx.z;
    const int kbase = sp * (NN / NSPLIT);

    float acc[2][8][4];
#pragma unroll
    for (int a = 0; a < 2; ++a)
#pragma unroll
        for (int b = 0; b < 8; ++b)
#pragma unroll
            for (int c = 0; c < 4; ++c) acc[a][b][c] = 0.f;

    load_chunk(g_Ah, g_Wth, NN, NN, sbase, m0, n0, kbase, tid);
    CP_COMMIT();
    const int NCH = (NN / NSPLIT) / BK;   // 16
    for (int c = 0; c < NCH; ++c) {
        if (c + 1 < NCH) {
            load_chunk(g_Ah, g_Wth, NN, NN, sbase + ((c + 1) & 1) * STAGE,
                       m0, n0, kbase + (c + 1) * BK, tid);
            CP_COMMIT();
            CP_WAIT1();
        } else {
            CP_WAIT0();
        }
        __syncthreads();
        compute_chunk(sbase + (c & 1) * STAGE, wm, wn, lane, acc);
        __syncthreads();
    }

    float* part = g_part + (size_t)sp * NN * KX;
    const int row0 = m0 + wm * 32 + (lane >> 2);
    const int col0 = n0 + wn * 64 + (lane & 3) * 2;
#pragma unroll
    for (int mi = 0; mi < 2; ++mi)
#pragma unroll
        for (int nj = 0; nj < 8; ++nj) {
            int r = row0 + mi * 16;
            int cc = col0 + nj * 8;
            float* p = part + (size_t)r * KX + cc;
            *(float2*)p = make_float2(acc[mi][nj][0], acc[mi][nj][1]);
            *(float2*)(p + (size_t)8 * KX) =
                make_float2(acc[mi][nj][2], acc[mi][nj][3]);
        }
}

// ---------------------------------------------------------------- reduce
// sums split-K partials and divides out the ASCALE attn scaling
__global__ void reduce_kernel(float* __restrict__ out) {
    int idx = blockIdx.x * blockDim.x + threadIdx.x;
    if (idx >= NN * KX / 4) return;
    const size_t stride = (size_t)NN * KX;
    float4 v = *(const float4*)(g_part + (size_t)idx * 4);
#pragma unroll
    for (int s = 1; s < NSPLIT; ++s) {
        const float4 w = *(const float4*)(g_part + s * stride + (size_t)idx * 4);
        v.x += w.x; v.y += w.y; v.z += w.z; v.w += w.w;
    }
    const float inv = 1.0f / ASCALE;
    v.x *= inv; v.y *= inv; v.z *= inv; v.w *= inv;
    int r = idx >> 7;
    int c4 = idx & 127;
    int col = c4 * 4;
    size_t half = (col < DD) ? 0 : (size_t)NN * DD;
    int lc = col & (DD - 1);
    *(float4*)(out + half + (size_t)r * DD + lc) = v;
}

// ---------------------------------------------------------------- edge bias
__global__ void edge_bias_kernel(const float* __restrict__ edge_attr,
                                 const int* __restrict__ edge_index,
                                 const float* __restrict__ w1,
                                 const float* __restrict__ b1,
                                 const float* __restrict__ w2,
                                 const float* __restrict__ b2,
                                 const float* __restrict__ dist_scale) {
    __shared__ float sw1[H4], sb1[H4], sw2[H4];
    if (threadIdx.x < H4) {
        sw1[threadIdx.x] = w1[threadIdx.x];
        sb1[threadIdx.x] = b1[threadIdx.x];
        sw2[threadIdx.x] = w2[threadIdx.x];
    }
    __syncthreads();
    int e = blockIdx.x * blockDim.x + threadIdx.x;
    if (e >= EE) return;
    float a = edge_attr[e];
    float acc = b2[0];
#pragma unroll
    for (int k = 0; k < H4; ++k) {
        float x = fmaf(a, sw1[k], sb1[k]);
        float sig = 1.f / (1.f + expf(-x));
        acc = fmaf(x * sig, sw2[k], acc);
    }
    acc = fmaf(dist_scale[0], a, acc);
    int i = edge_index[e];
    int j = edge_index[EE + e];
    if ((unsigned)i < NN && (unsigned)j < NN)
        atomicAdd(&g_scores[(size_t)i * NN + j], acc);
}

// ---------------------------------------------------------------- softmax
// reads fp32 logits, writes attn * 256 as single fp16
__device__ __forceinline__ float warp_max(float v) {
#pragma unroll
    for (int o = 16; o > 0; o >>= 1) v = fmaxf(v, __shfl_xor_sync(0xffffffffu, v, o));
    return v;
}
__device__ __forceinline__ float warp_sum(float v) {
#pragma unroll
    for (int o = 16; o > 0; o >>= 1) v += __shfl_xor_sync(0xffffffffu, v, o);
    return v;
}

__global__ void softmax_kernel() {
    const int row = blockIdx.x;
    const int t = threadIdx.x;
    const float4* rp = (const float4*)&g_scores[(size_t)row * NN];
    __half2* rh = (__half2*)&g_Ah[(size_t)row * NN];

    float4 v[8];
    float m = -3.4e38f;
#pragma unroll
    for (int i = 0; i < 8; ++i) {
        v[i] = rp[t + i * 256];
        m = fmaxf(m, fmaxf(fmaxf(v[i].x, v[i].y), fmaxf(v[i].z, v[i].w)));
    }
    __shared__ float red[8];
    int lane = t & 31, wid = t >> 5;
    m = warp_max(m);
    if (lane == 0) red[wid] = m;
    __syncthreads();
    float bm = red[0];
#pragma unroll
    for (int i = 1; i < 8; ++i) bm = fmaxf(bm, red[i]);
    __syncthreads();

    float s = 0.f;
#pragma unroll
    for (int i = 0; i < 8; ++i) {
        v[i].x = expf(v[i].x - bm);
        v[i].y = expf(v[i].y - bm);
        v[i].z = expf(v[i].z - bm);
        v[i].w = expf(v[i].w - bm);
        s += (v[i].x + v[i].y) + (v[i].z + v[i].w);
    }
    s = warp_sum(s);
    if (lane == 0) red[wid] = s;
    __syncthreads();
    float bs = 0.f;
#pragma unroll
    for (int i = 0; i < 8; ++i) bs += red[i];
    const float invs = ASCALE / bs;

#pragma unroll
    for (int i = 0; i < 8; ++i) {
        int idx = t + i * 256;
        rh[2 * idx]     = __floats2half2_rn(v[i].x * invs, v[i].y * invs);
        rh[2 * idx + 1] = __floats2half2_rn(v[i].z * invs, v[i].w * invs);
    }
}

// ---------------------------------------------------------------- launch
extern "C" void kernel_launch(void* const* d_in, const int* in_sizes, int n_in,
                              void* d_out, int out_size) {
    const float* mag        = (const float*)d_in[0];
    const float* phase      = (const float*)d_in[1];
    const float* edge_attr  = (const float*)d_in[2];
    const int*   edge_index = (const int*)d_in[3];
    const float* w1         = (const float*)d_in[4];
    const float* b1         = (const float*)d_in[5];
    const float* w2         = (const float*)d_in[6];
    const float* b2         = (const float*)d_in[7];
    const float* dist_scale = (const float*)d_in[8];
    float*       out        = (float*)d_out;

    cudaFuncSetAttribute(syrk_kernel,
                         cudaFuncAttributeMaxDynamicSharedMemorySize, DSMEM_BYTES);
    cudaFuncSetAttribute(gemm2_kernel,
                         cudaFuncAttributeMaxDynamicSharedMemorySize, DSMEM_BYTES);

    prep1_kernel<<<(NN * DD + 255) / 256, 256>>>(mag, phase);          // #1
    prep2_kernel<<<dim3(NN / 32, DD / 32), dim3(32, 32)>>>(mag, phase); // #2
    probe_kernel<<<1, 32>>>();                                         // #3
    syrk_kernel<<<dim3(NN / BN, NN / BM), NTHREADS, DSMEM_BYTES>>>();  // #4 -> profiled
    edge_bias_kernel<<<(EE + 255) / 256, 256>>>(edge_attr, edge_index,
                                                w1, b1, w2, b2, dist_scale);
    softmax_kernel<<<NN, 256>>>();
    gemm2_kernel<<<dim3(KX / BN, NN / BM, NSPLIT), NTHREADS, DSMEM_BYTES>>>();
    reduce_kernel<<<(NN * KX / 4 + 255) / 256, 256>>>(out);
}